// round 3
// baseline (speedup 1.0000x reference)
#include <cuda_runtime.h>
#include <cuda_bf16.h>

// Problem constants (fixed by the dataset)
#define NN   2048   // number of nodes
#define ZD   64     // z_dim
#define HID  64     // hidden
#define TJ   256    // j-columns per block (== blockDim.x)
#define RI   32     // i-rows per block
#define KC   8      // k-chunk held in registers

// Scratch for the projection stage (allocation-free rule: __device__ globals)
__device__ float g_PI [NN * HID];   // pi[n][h] = z[n]@W1[:ZD] + b1[h]
__device__ float g_PJt[HID * NN];   // pj^T[h][n] = z[n]@W1[ZD:]  (k-major for coalesced pair-stage loads)

// ---------------------------------------------------------------------------
// Stage 1: P = z @ W1 (both halves), b1 folded into pi, pj stored transposed.
// 2048 blocks x 128 threads; trivial cost (~17 MFMA).
// ---------------------------------------------------------------------------
__global__ void edge_proj_kernel(const float* __restrict__ z,
                                 const float* __restrict__ W1,
                                 const float* __restrict__ b1) {
    __shared__ float zs[ZD];
    const int n = blockIdx.x;
    const int t = threadIdx.x;          // 0..127
    if (t < ZD) zs[t] = z[n * ZD + t];
    __syncthreads();

    const int half = t >> 6;            // 0 -> pi (W1 rows 0..63), 1 -> pj (rows 64..127)
    const int h    = t & 63;
    const float* w = W1 + (half * ZD) * HID + h;   // column h, stride HID over d

    float acc = 0.f;
    #pragma unroll 16
    for (int d = 0; d < ZD; d++)
        acc = fmaf(zs[d], w[d * HID], acc);

    if (half == 0) g_PI [n * HID + h] = acc + b1[h];
    else           g_PJt[h * NN  + n] = acc;
}

// ---------------------------------------------------------------------------
// Stage 2: pairwise MLP.
//   out[i][j] = sigmoid( sum_k relu(pi[i][k] + pj[j][k]) * W2[k] + b2 )
// Each thread: one j column, RI=32 i rows. pj chunk lives in registers and is
// reused across all RI i's; pi comes from smem via broadcast LDS.128.
// Grid: (NN/TJ, NN/RI) = (8, 64); block 256.
// ---------------------------------------------------------------------------
__global__ void __launch_bounds__(TJ, 2)
edge_pair_kernel(const float* __restrict__ W2,
                 const float* __restrict__ b2,
                 float* __restrict__ out) {
    __shared__ __align__(16) float s_pi[RI * HID];
    __shared__ float s_w2[HID];

    const int j  = blockIdx.x * TJ + threadIdx.x;
    const int i0 = blockIdx.y * RI;

    // Load pi tile (RI x HID = 2048 floats) and W2 into smem (coalesced)
    #pragma unroll
    for (int idx = threadIdx.x; idx < RI * HID; idx += TJ)
        s_pi[idx] = g_PI[i0 * HID + idx];
    if (threadIdx.x < HID) s_w2[threadIdx.x] = W2[threadIdx.x];
    __syncthreads();

    float acc[RI];
    #pragma unroll
    for (int i = 0; i < RI; i++) acc[i] = 0.f;

    #pragma unroll 1
    for (int kc = 0; kc < HID; kc += KC) {
        // Per-thread pj chunk (coalesced LDG from transposed layout) + uniform W2 chunk
        float pj_r[KC], w2_r[KC];
        #pragma unroll
        for (int kk = 0; kk < KC; kk++) {
            pj_r[kk] = g_PJt[(kc + kk) * NN + j];
            w2_r[kk] = s_w2[kc + kk];
        }
        // Reuse the chunk across all RI i-rows
        #pragma unroll
        for (int i = 0; i < RI; i++) {
            const float4* p4 =
                reinterpret_cast<const float4*>(&s_pi[i * HID + kc]);
            #pragma unroll
            for (int q = 0; q < KC / 4; q++) {
                float4 a = p4[q];                         // broadcast LDS.128
                float s0 = a.x + pj_r[4 * q + 0];
                float s1 = a.y + pj_r[4 * q + 1];
                float s2 = a.z + pj_r[4 * q + 2];
                float s3 = a.w + pj_r[4 * q + 3];
                acc[i] = fmaf(fmaxf(s0, 0.f), w2_r[4 * q + 0], acc[i]);
                acc[i] = fmaf(fmaxf(s1, 0.f), w2_r[4 * q + 1], acc[i]);
                acc[i] = fmaf(fmaxf(s2, 0.f), w2_r[4 * q + 2], acc[i]);
                acc[i] = fmaf(fmaxf(s3, 0.f), w2_r[4 * q + 3], acc[i]);
            }
        }
    }

    const float b2v = b2[0];
    #pragma unroll
    for (int i = 0; i < RI; i++) {
        float x = acc[i] + b2v;
        out[(i0 + i) * NN + j] = 1.0f / (1.0f + __expf(-x));  // sigmoid
    }
}

// ---------------------------------------------------------------------------
// Inputs per metadata order: z, W1, b1, W2, b2. Output: float32 [2048*2048].
// Graph-capturable: two plain launches, no sync, no allocation.
// ---------------------------------------------------------------------------
extern "C" void kernel_launch(void* const* d_in, const int* in_sizes, int n_in,
                              void* d_out, int out_size) {
    const float* z  = (const float*)d_in[0];
    const float* W1 = (const float*)d_in[1];
    const float* b1 = (const float*)d_in[2];
    const float* W2 = (const float*)d_in[3];
    const float* b2 = (const float*)d_in[4];
    float* out = (float*)d_out;

    edge_proj_kernel<<<NN, 128>>>(z, W1, b1);

    dim3 grid(NN / TJ, NN / RI);
    edge_pair_kernel<<<grid, TJ>>>(W2, b2, out);
}

// round 5
// speedup vs baseline: 1.1665x; 1.1665x over previous
#include <cuda_runtime.h>
#include <cuda_bf16.h>

// Problem constants (fixed by the dataset)
#define NN   2048   // nodes
#define ZD   64     // z_dim
#define HID  64     // hidden
#define TJ   256    // j-columns per block (== blockDim.x)
#define RI   16     // i-rows per block (packed accumulators: 2 regs each)
#define NPB  8      // nodes per block in stage 1

// Scratch (allocation-free rule: __device__ globals)
__device__ float g_PI [NN * HID];   // pi[n][h] = z@W1[:ZD] + b1  (row-major)
__device__ float g_PJ2[HID * NN];   // pj^T, pair-interleaved: [(h>>1)][n][h&1]
__device__ float g_A  [NN];         // a_i = sum_k pi[i,k] * w2[k]
__device__ float g_B  [NN];         // b_j = sum_k pj[j,k] * w2[k]

// sm_103a packed fp32 ops (FFMA2-class, fma pipe)
#define F32X2_ADD(d, a, b) \
    asm("add.rn.f32x2 %0, %1, %2;" : "=l"(d) : "l"(a), "l"(b))
#define F32X2_FMA(d, a, b, c) \
    asm("fma.rn.f32x2 %0, %1, %2, %3;" : "=l"(d) : "l"(a), "l"(b), "l"(c))

// ---------------------------------------------------------------------------
// Stage 1: projections + rank-1 terms. Each block does NPB nodes so W1 stays
// L1-resident after the first node (L2 traffic 64MB -> 8MB vs R3).
//   half 0 threads (t<64):  pi[n][h] = z[n]@W1[:ZD,h] + b1[h]   -> g_PI
//   half 1 threads (t>=64): pj[n][h] = z[n]@W1[ZD:,h]           -> g_PJ2 (pair-interleaved)
// Fused: a[n] = sum_h pi*w2, b[n] = sum_h pj*w2 via shuffle reduce.
// ---------------------------------------------------------------------------
__global__ void edge_proj_kernel(const float* __restrict__ z,
                                 const float* __restrict__ W1,
                                 const float* __restrict__ b1,
                                 const float* __restrict__ W2) {
    __shared__ float zs[ZD];
    __shared__ float red[4];
    const int t    = threadIdx.x;            // 0..127
    const int half = t >> 6;
    const int h    = t & 63;
    const float* w  = W1 + (half * ZD) * HID + h;   // column h of the right half
    const float b1v = b1[h];
    const float w2v = W2[h];

    for (int rep = 0; rep < NPB; rep++) {
        const int n = blockIdx.x * NPB + rep;
        if (t < ZD) zs[t] = z[n * ZD + t];
        __syncthreads();

        float acc = 0.f;
        #pragma unroll
        for (int d = 0; d < ZD; d++)
            acc = fmaf(zs[d], w[d * HID], acc);      // W1 loads: L1 hits after rep 0

        const float val = (half == 0) ? (acc + b1v) : acc;
        if (half == 0) g_PI [n * HID + h] = val;
        else           g_PJ2[(h >> 1) * (2 * NN) + 2 * n + (h & 1)] = val;

        // fused a/b reduction
        float v = val * w2v;
        #pragma unroll
        for (int off = 16; off; off >>= 1)
            v += __shfl_down_sync(0xffffffffu, v, off);
        if ((t & 31) == 0) red[t >> 5] = v;
        __syncthreads();
        if (t == 0)  g_A[n] = red[0] + red[1];
        if (t == 64) g_B[n] = red[2] + red[3];
        __syncthreads();   // protect zs/red before next rep
    }
}

// ---------------------------------------------------------------------------
// Stage 2: pairwise core, relu removed via relu(x) = (x+|x|)/2:
//   logit = 0.5*(a_i + b_j + sum_k |pi+pj|*w2_k) + b2
// Inner loop per 2 k's: add.rn.f32x2, 64-bit AND (abs, alu pipe), fma.rn.f32x2.
// Each thread: one j column, RI=16 i rows; pj/w2 chunks in regs reused over i.
// ---------------------------------------------------------------------------
__global__ void __launch_bounds__(TJ, 3)
edge_pair_kernel(const float* __restrict__ W2,
                 const float* __restrict__ b2,
                 float* __restrict__ out) {
    __shared__ __align__(16) float s_pi[RI * HID];
    __shared__ __align__(8)  float s_w2[HID];
    __shared__ float s_lin[RI];

    const int j  = blockIdx.x * TJ + threadIdx.x;
    const int i0 = blockIdx.y * RI;

    #pragma unroll
    for (int idx = threadIdx.x; idx < RI * HID; idx += TJ)
        s_pi[idx] = g_PI[i0 * HID + idx];
    if (threadIdx.x < HID) s_w2[threadIdx.x] = W2[threadIdx.x];
    if (threadIdx.x < RI)  s_lin[threadIdx.x] = g_A[i0 + threadIdx.x];
    __syncthreads();

    unsigned long long acc[RI];
    #pragma unroll
    for (int i = 0; i < RI; i++) acc[i] = 0ULL;

    const unsigned long long* w2p =
        reinterpret_cast<const unsigned long long*>(s_w2);
    const unsigned long long ABSM = 0x7fffffff7fffffffULL;

    #pragma unroll 1
    for (int kc = 0; kc < HID; kc += 8) {
        const int p0 = kc >> 1;                    // k-pair index base
        unsigned long long pjr[4], w2r[4];
        #pragma unroll
        for (int q = 0; q < 4; q++) {
            // coalesced LDG.64: consecutive j -> consecutive float2
            pjr[q] = *reinterpret_cast<const unsigned long long*>(
                         &g_PJ2[(p0 + q) * (2 * NN) + 2 * j]);
            w2r[q] = w2p[p0 + q];
        }
        #pragma unroll
        for (int i = 0; i < RI; i++) {
            const ulonglong2* pp =
                reinterpret_cast<const ulonglong2*>(&s_pi[i * HID + kc]);
            ulonglong2 a0 = pp[0];                 // LDS.128: pairs p0, p0+1
            ulonglong2 a1 = pp[1];                 // LDS.128: pairs p0+2, p0+3
            unsigned long long s;
            F32X2_ADD(s, a0.x, pjr[0]); s &= ABSM; F32X2_FMA(acc[i], s, w2r[0], acc[i]);
            F32X2_ADD(s, a0.y, pjr[1]); s &= ABSM; F32X2_FMA(acc[i], s, w2r[1], acc[i]);
            F32X2_ADD(s, a1.x, pjr[2]); s &= ABSM; F32X2_FMA(acc[i], s, w2r[2], acc[i]);
            F32X2_ADD(s, a1.y, pjr[3]); s &= ABSM; F32X2_FMA(acc[i], s, w2r[3], acc[i]);
        }
    }

    const float b2v = b2[0];
    const float bj  = g_B[j];
    #pragma unroll
    for (int i = 0; i < RI; i++) {
        const float lo = __uint_as_float((unsigned)(acc[i] & 0xffffffffULL));
        const float hi = __uint_as_float((unsigned)(acc[i] >> 32));
        const float x  = fmaf(0.5f, s_lin[i] + bj + (lo + hi), b2v);
        out[(i0 + i) * NN + j] = 1.0f / (1.0f + __expf(-x));
    }
}

// ---------------------------------------------------------------------------
// Inputs per metadata order: z, W1, b1, W2, b2. Output: float32 [2048*2048].
// Graph-capturable: two launches, no sync, no allocation.
// ---------------------------------------------------------------------------
extern "C" void kernel_launch(void* const* d_in, const int* in_sizes, int n_in,
                              void* d_out, int out_size) {
    const float* z  = (const float*)d_in[0];
    const float* W1 = (const float*)d_in[1];
    const float* b1 = (const float*)d_in[2];
    const float* W2 = (const float*)d_in[3];
    const float* b2 = (const float*)d_in[4];
    float* out = (float*)d_out;

    edge_proj_kernel<<<NN / NPB, 128>>>(z, W1, b1, W2);

    dim3 grid(NN / TJ, NN / RI);
    edge_pair_kernel<<<grid, TJ>>>(W2, b2, out);
}